// round 17
// baseline (speedup 1.0000x reference)
#include <cstdint>
#include <cuda_runtime.h>
#include <mma.h>

using namespace nvcuda;

// Problem constants (fixed shapes per reference setup_inputs)
#define NB   8
#define LQ   1024
#define CD   256
#define NH   8
#define NPT  4
#define HD   32
#define HH   128
#define WWp  128
#define HWSZ (HH * WWp)
#define NQ   (NB * LQ)      // 8192

// ---------------- scratch (device globals; no allocations allowed) ----------
__device__ float4 g_samp[(size_t)NQ * NH * NPT];      // (x_pix, y_pix, attn_w, _)
__device__ float  g_U[(size_t)NH * NQ * CD];          // gathered rows (tf32-rounded)
__device__ float  g_sw[(size_t)NQ * NH];              // sum of effective weights
__device__ float  g_S[(size_t)NQ * CD];               // sampled values (tf32-rounded)
__device__ float  g_P[(size_t)NQ * 96];               // offsets(64) | attn logits(32)
__device__ float  g_Wvr[CD * CD];                     // tf32-rounded Wv
__device__ float  g_Wor[CD * CD];                     // tf32-rounded Wout
__device__ float  g_Wq[CD * 96];                      // tf32-rounded [Woff | Wattn]

// ---------------- cp.async helpers ------------------------------------------
__device__ __forceinline__ void cpasync16(void* smem_dst, const void* gmem_src) {
    unsigned int s = (unsigned int)__cvta_generic_to_shared(smem_dst);
    asm volatile("cp.async.cg.shared.global [%0], [%1], 16;" :: "r"(s), "l"(gmem_src));
}
__device__ __forceinline__ void cpasync_commit() {
    asm volatile("cp.async.commit_group;");
}
__device__ __forceinline__ void cpasync_wait0() {
    asm volatile("cp.async.wait_group 0;");
}

// =====================================================================
// kernel 0: pre-round weights to tf32 (RN); build concatenated Wq
// =====================================================================
__global__ void __launch_bounds__(256) k_roundW(
    const float* __restrict__ Wv,  const float* __restrict__ Wo,
    const float* __restrict__ Woff, const float* __restrict__ Wattn)
{
    int id = blockIdx.x * 256 + threadIdx.x;          // 0..65535
    g_Wvr[id] = wmma::__float_to_tf32(Wv[id]);
    g_Wor[id] = wmma::__float_to_tf32(Wo[id]);
    if (id < CD * 96) {
        int k = id / 96, c = id % 96;
        float v = (c < 64) ? Woff[k * 64 + c] : Wattn[k * 32 + (c - 64)];
        g_Wq[id] = wmma::__float_to_tf32(v);
    }
}

// =====================================================================
// kernel 1a: offsets/logits GEMM  P[8192,96] = query @ Wq   (64 CTAs, 1 wave)
// =====================================================================
#define OLDA 20
#define OLDB 100

struct __align__(16) SmemOff {
    float a[2][128 * OLDA];       // 20.5 KB
    float b[2][16 * OLDB];        // 12.8 KB
};

__global__ void __launch_bounds__(256)
k_offgemm(const float* __restrict__ query)
{
    __shared__ SmemOff sm;
    int tid = threadIdx.x;
    int wid = tid >> 5;
    int wr = wid & 3;             // 4 row groups of 32
    int wc = wid >> 2;            // 2 col groups of 48
    int m0 = blockIdx.x * 128;

    wmma::fragment<wmma::accumulator, 16, 16, 8, float> acc[2][3];
    #pragma unroll
    for (int i = 0; i < 2; i++)
        #pragma unroll
        for (int j = 0; j < 3; j++) wmma::fill_fragment(acc[i][j], 0.0f);

    auto load_tiles = [&](int buf, int k0) {
        #pragma unroll
        for (int i = 0; i < 2; i++) {
            int f4 = tid + i * 256;
            int r = f4 >> 2, c4 = f4 & 3;
            cpasync16(&sm.a[buf][r * OLDA + c4 * 4],
                      query + (size_t)(m0 + r) * CD + k0 + c4 * 4);
        }
        #pragma unroll
        for (int i = 0; i < 2; i++) {
            int f = tid + i * 256;
            if (f < 384) {
                int r = f / 24, c4 = f % 24;
                cpasync16(&sm.b[buf][r * OLDB + c4 * 4],
                          g_Wq + (size_t)(k0 + r) * 96 + c4 * 4);
            }
        }
        cpasync_commit();
    };

    load_tiles(0, 0);

    const int NIT = CD / 16;      // 16
    for (int it = 0; it < NIT; ++it) {
        cpasync_wait0();
        __syncthreads();
        if (it + 1 < NIT) load_tiles((it + 1) & 1, (it + 1) * 16);

        int buf = it & 1;
        #pragma unroll
        for (int kk = 0; kk < 16; kk += 8) {
            wmma::fragment<wmma::matrix_a, 16, 16, 8, wmma::precision::tf32, wmma::row_major> af[2];
            wmma::fragment<wmma::matrix_b, 16, 16, 8, wmma::precision::tf32, wmma::row_major> bf[3];
            #pragma unroll
            for (int i = 0; i < 2; i++) {
                wmma::load_matrix_sync(af[i], &sm.a[buf][(wr * 32 + i * 16) * OLDA + kk], OLDA);
                #pragma unroll
                for (int e = 0; e < af[i].num_elements; e++)
                    af[i].x[e] = wmma::__float_to_tf32(af[i].x[e]);   // query is raw fp32
            }
            #pragma unroll
            for (int j = 0; j < 3; j++)
                wmma::load_matrix_sync(bf[j], &sm.b[buf][kk * OLDB + wc * 48 + j * 16], OLDB);
            #pragma unroll
            for (int i = 0; i < 2; i++)
                #pragma unroll
                for (int j = 0; j < 3; j++)
                    wmma::mma_sync(acc[i][j], af[i], bf[j], acc[i][j]);
        }
        __syncthreads();
    }

    #pragma unroll
    for (int i = 0; i < 2; i++)
        #pragma unroll
        for (int j = 0; j < 3; j++)
            wmma::store_matrix_sync(g_P + (size_t)(m0 + wr * 32 + i * 16) * 96 + wc * 48 + j * 16,
                                    acc[i][j], 96, wmma::mem_row_major);
}

// =====================================================================
// kernel 1b: finalize — softmax over points + pixel coords -> g_samp
// =====================================================================
__global__ void __launch_bounds__(256) k_finalize(
    const float* __restrict__ refp,
    const float* __restrict__ boff, const float* __restrict__ battn)
{
    int id = blockIdx.x * 256 + threadIdx.x;   // 0..262143 = bq*32 + t32
    int bq = id >> 5, t32 = id & 31;
    int h = t32 >> 2, p = t32 & 3;

    const float* prow = g_P + (size_t)bq * 96;
    float l0 = prow[64 + h * 4 + 0] + battn[h * 4 + 0];
    float l1 = prow[64 + h * 4 + 1] + battn[h * 4 + 1];
    float l2 = prow[64 + h * 4 + 2] + battn[h * 4 + 2];
    float l3 = prow[64 + h * 4 + 3] + battn[h * 4 + 3];
    float m  = fmaxf(fmaxf(l0, l1), fmaxf(l2, l3));
    float e0 = __expf(l0 - m), e1 = __expf(l1 - m);
    float e2 = __expf(l2 - m), e3 = __expf(l3 - m);
    float inv = 1.0f / (e0 + e1 + e2 + e3);
    float ep  = (p == 0) ? e0 : (p == 1) ? e1 : (p == 2) ? e2 : e3;
    float w   = ep * inv;

    float ox = prow[(h * NPT + p) * 2 + 0] + boff[(h * NPT + p) * 2 + 0];
    float oy = prow[(h * NPT + p) * 2 + 1] + boff[(h * NPT + p) * 2 + 1];
    float refx = refp[bq * 2 + 0];
    float refy = refp[bq * 2 + 1];
    // grid_sample align_corners=False: pix = (ref + off/Dim)*Dim - 0.5
    float x = refx * (float)WWp + ox - 0.5f;
    float y = refy * (float)HH  + oy - 0.5f;
    g_samp[(size_t)bq * (NH * NPT) + t32] = make_float4(x, y, w, 0.f);
}

// =====================================================================
// kernel 2: gather with cross-head corner DEDUP.
// Block = query. The 32 (head,point) samples cluster near the reference
// point, so their 128 corner refs hit ~15-25 distinct rows. Warp 0 scatters
// weights into a 12x12 local grid (per-head columns, deterministic), builds
// an ordered active-cell list; then each thread owns ONE channel and loops
// over active cells, loading each row value ONCE and feeding 8 head
// accumulators. L1 bytes/query: 128KB -> ~20KB.
// Out-of-grid points (|offset|>~4.5px, ~5.6 sigma) use an exact fallback.
// =====================================================================
#define GW   12
#define GC   (GW * GW)       // 144

__global__ void __launch_bounds__(256) k_gather(const float* __restrict__ memory,
                                                const float* __restrict__ refp)
{
    __shared__ float wgt[GC][NH];        // 4.6 KB
    __shared__ int   active[GC];
    __shared__ int   counts[2];          // [0]=nactive, [1]=noutlier
    __shared__ int   outlist[32];
    __shared__ int   pix_[32], piy_[32], pin_[32];
    __shared__ float pcw_[32][4];

    int bq  = blockIdx.x;
    int tid = threadIdx.x;
    int b   = bq >> 10;

    // zero weight grid
    for (int i = tid; i < GC * NH; i += 256) ((float*)wgt)[i] = 0.f;
    __syncthreads();

    // grid origin from reference point
    float refx = refp[bq * 2 + 0] * (float)WWp - 0.5f;
    float refy = refp[bq * 2 + 1] * (float)HH  - 0.5f;
    int cx0 = (int)floorf(refx) - 5;
    int cy0 = (int)floorf(refy) - 5;

    // ---- phase A (warp 0 only; program-ordered, no atomics) ----
    if (tid < 32) {
        // A1: per-(h,p) corner data
        float4 sm = g_samp[(size_t)bq * (NH * NPT) + tid];
        float x = sm.x, y = sm.y, w = sm.z;
        float xf = floorf(x), yf = floorf(y);
        int ix = (int)xf, iy = (int)yf;
        float fx = x - xf, fy = y - yf;
        pcw_[tid][0] = w * (1.0f - fy) * (1.0f - fx);
        pcw_[tid][1] = w * (1.0f - fy) * fx;
        pcw_[tid][2] = w * fy * (1.0f - fx);
        pcw_[tid][3] = w * fy * fx;
        pix_[tid] = ix; piy_[tid] = iy;
        int gx = ix - cx0, gy = iy - cy0;
        pin_[tid] = (gx >= 0 && gx <= GW - 2 && gy >= 0 && gy <= GW - 2);
        __syncwarp();

        // A2: 8 column-owner threads accumulate weights (deterministic)
        if (tid < NH) {
            float ssum = 0.f;
            #pragma unroll
            for (int p = 0; p < NPT; p++) {
                int t32 = tid * NPT + p;
                int ix2 = pix_[t32], iy2 = piy_[t32];
                if (pin_[t32]) {
                    int gx2 = ix2 - cx0, gy2 = iy2 - cy0;
                    #pragma unroll
                    for (int cy = 0; cy < 2; cy++)
                        #pragma unroll
                        for (int cx = 0; cx < 2; cx++) {
                            int xx = ix2 + cx, yy = iy2 + cy;
                            if ((unsigned)xx < WWp && (unsigned)yy < HH) {
                                float wv = pcw_[t32][cy * 2 + cx];
                                wgt[(gy2 + cy) * GW + (gx2 + cx)][tid] += wv;
                                ssum += wv;
                            }
                        }
                } else {
                    #pragma unroll
                    for (int cy = 0; cy < 2; cy++)
                        #pragma unroll
                        for (int cx = 0; cx < 2; cx++) {
                            int xx = ix2 + cx, yy = iy2 + cy;
                            if ((unsigned)xx < WWp && (unsigned)yy < HH)
                                ssum += pcw_[t32][cy * 2 + cx];
                        }
                }
            }
            g_sw[(size_t)bq * NH + tid] = ssum;
        }
        __syncwarp();

        // A3: ordered outlier list (ballot compaction)
        {
            unsigned m = __ballot_sync(0xffffffff, pin_[tid] == 0);
            if (!pin_[tid]) outlist[__popc(m & ((1u << tid) - 1u))] = tid;
            if (tid == 0) counts[1] = __popc(m);
        }

        // A4: ordered active-cell list (5 ballot chunks over 144 cells)
        {
            int base = 0;
            for (int c0 = 0; c0 < GC; c0 += 32) {
                int cidx = c0 + tid;
                bool nz = false;
                if (cidx < GC) {
                    float any = 0.f;
                    #pragma unroll
                    for (int h = 0; h < NH; h++) any += fabsf(wgt[cidx][h]);
                    nz = (any != 0.f);
                }
                unsigned m = __ballot_sync(0xffffffff, nz);
                if (nz) active[base + __popc(m & ((1u << tid) - 1u))] = cidx;
                base += __popc(m);
            }
            if (tid == 0) counts[0] = base;
        }
    }
    __syncthreads();

    // ---- phase B: thread = channel; loop active cells, 8 heads per value ----
    const float* mb = memory + (size_t)b * HWSZ * CD;
    float acc[NH] = {0.f, 0.f, 0.f, 0.f, 0.f, 0.f, 0.f, 0.f};
    int nc = counts[0];
    for (int i = 0; i < nc; i++) {
        int cidx = active[i];
        int gy = cidx / GW, gx = cidx - gy * GW;
        int yy = cy0 + gy, xx = cx0 + gx;      // in-bounds by construction
        float val = mb[(size_t)(yy * WWp + xx) * CD + tid];
        float4 w0 = *(float4*)&wgt[cidx][0];
        float4 w1 = *(float4*)&wgt[cidx][4];
        acc[0] += w0.x * val; acc[1] += w0.y * val;
        acc[2] += w0.z * val; acc[3] += w0.w * val;
        acc[4] += w1.x * val; acc[5] += w1.y * val;
        acc[6] += w1.z * val; acc[7] += w1.w * val;
    }

    // ---- exact fallback for out-of-grid points (rare) ----
    int no = counts[1];
    for (int i = 0; i < no; i++) {
        int t32 = outlist[i];
        int h = t32 >> 2;
        int ix = pix_[t32], iy = piy_[t32];
        #pragma unroll
        for (int cy = 0; cy < 2; cy++)
            #pragma unroll
            for (int cx = 0; cx < 2; cx++) {
                int xx = ix + cx, yy = iy + cy;
                if ((unsigned)xx < WWp && (unsigned)yy < HH)
                    acc[h] += pcw_[t32][cy * 2 + cx] *
                              mb[(size_t)(yy * WWp + xx) * CD + tid];
            }
    }

    // write U rows (thread = channel; each head's 256 floats contiguous)
    #pragma unroll
    for (int h = 0; h < NH; h++)
        g_U[((size_t)h * NQ + bq) * CD + tid] = wmma::__float_to_tf32(acc[h]);
}

// =====================================================================
// kernel 3: per-head value projection (inputs pre-rounded: no in-reg cvt)
// =====================================================================
#define SBM 128
#define SBK 16
#define SLDA 20
#define SLDB 36
#define SLDC 36

struct __align__(16) SmemS {
    union {
        struct { float a[2][SBM * SLDA]; float b[2][SBK * SLDB]; } ab;
        float c[SBM * SLDC];
    };
};

__global__ void __launch_bounds__(256)
k_gemmS(const float* __restrict__ bv)
{
    __shared__ SmemS sm;
    int h   = blockIdx.y;
    int m0  = blockIdx.x * SBM;
    int tid = threadIdx.x;
    int warpId = tid >> 5;

    const float* A = g_U + (size_t)h * NQ * CD;

    wmma::fragment<wmma::accumulator, 16, 16, 8, float> acc[2];
    wmma::fill_fragment(acc[0], 0.0f);
    wmma::fill_fragment(acc[1], 0.0f);

    auto load_tiles = [&](int buf, int k0) {
        #pragma unroll
        for (int i = 0; i < 2; i++) {
            int f4 = tid + i * 256;
            int r = f4 >> 2, c4 = f4 & 3;
            cpasync16(&sm.ab.a[buf][r * SLDA + c4 * 4],
                      A + (size_t)(m0 + r) * CD + k0 + c4 * 4);
        }
        if (tid < 128) {
            int r = tid >> 3, c4 = tid & 7;
            cpasync16(&sm.ab.b[buf][r * SLDB + c4 * 4],
                      g_Wvr + (size_t)(k0 + r) * CD + h * 32 + c4 * 4);
        }
        cpasync_commit();
    };

    load_tiles(0, 0);

    const int NIT = CD / SBK;
    for (int it = 0; it < NIT; ++it) {
        cpasync_wait0();
        __syncthreads();
        if (it + 1 < NIT) load_tiles((it + 1) & 1, (it + 1) * SBK);

        int buf = it & 1;
        #pragma unroll
        for (int kk = 0; kk < SBK; kk += 8) {
            wmma::fragment<wmma::matrix_a, 16, 16, 8, wmma::precision::tf32, wmma::row_major> af;
            wmma::fragment<wmma::matrix_b, 16, 16, 8, wmma::precision::tf32, wmma::row_major> bf[2];
            wmma::load_matrix_sync(af, &sm.ab.a[buf][(warpId * 16) * SLDA + kk], SLDA);
            #pragma unroll
            for (int j = 0; j < 2; j++) {
                wmma::load_matrix_sync(bf[j], &sm.ab.b[buf][kk * SLDB + j * 16], SLDB);
                wmma::mma_sync(acc[j], af, bf[j], acc[j]);
            }
        }
        __syncthreads();
    }

    #pragma unroll
    for (int j = 0; j < 2; j++)
        wmma::store_matrix_sync(&sm.c[(warpId * 16) * SLDC + j * 16], acc[j],
                                SLDC, wmma::mem_row_major);
    __syncthreads();

    // epilogue: + s*bv in fp32, then tf32-round for gemmO's A operand
    #pragma unroll
    for (int i = 0; i < 4; i++) {
        int f4 = i * 256 + tid;
        int r = f4 >> 3, c4 = f4 & 7;
        float s = g_sw[(size_t)(m0 + r) * NH + h];
        float4 v  = *(float4*)&sm.c[r * SLDC + c4 * 4];
        float4 bb = *(const float4*)(bv + h * 32 + c4 * 4);
        v.x = wmma::__float_to_tf32(v.x + s * bb.x);
        v.y = wmma::__float_to_tf32(v.y + s * bb.y);
        v.z = wmma::__float_to_tf32(v.z + s * bb.z);
        v.w = wmma::__float_to_tf32(v.w + s * bb.w);
        *(float4*)&g_S[(size_t)(m0 + r) * CD + h * 32 + c4 * 4] = v;
    }
}

// =====================================================================
// kernel 4: output projection GEMM (BM=128 x BN=64, 3 stages; no in-reg cvt)
// =====================================================================
#define BM 128
#define BN 64
#define BK 16
#define NSTG 3
#define LDA 20
#define LDB 68
#define LDC 68

struct __align__(16) SmemGemm {
    union {
        struct { float a[NSTG][BM * LDA]; float b[NSTG][BK * LDB]; } ab;
        float c[BM * LDC];
    };
};

__global__ void __launch_bounds__(256)
k_gemmO(const float* __restrict__ bias, float* __restrict__ out)
{
    __shared__ SmemGemm sm;
    const float* A = (const float*)g_S;

    int n0 = blockIdx.x * BN;
    int m0 = blockIdx.y * BM;
    int tid = threadIdx.x;
    int warpId = tid >> 5;
    int wr = warpId >> 1;
    int wc = warpId & 1;

    wmma::fragment<wmma::accumulator, 16, 16, 8, float> acc[2][2];
    #pragma unroll
    for (int i = 0; i < 2; i++)
        #pragma unroll
        for (int j = 0; j < 2; j++) wmma::fill_fragment(acc[i][j], 0.0f);

    auto load_tiles = [&](int buf, int k0) {
        #pragma unroll
        for (int i = 0; i < 2; i++) {
            int f4 = tid + i * 256;
            int r = f4 >> 2, c4 = f4 & 3;
            cpasync16(&sm.ab.a[buf][r * LDA + c4 * 4],
                      A + (size_t)(m0 + r) * CD + k0 + c4 * 4);
        }
        {
            int r = tid >> 4, c4 = tid & 15;
            cpasync16(&sm.ab.b[buf][r * LDB + c4 * 4],
                      g_Wor + (size_t)(k0 + r) * CD + n0 + c4 * 4);
        }
        cpasync_commit();
    };

    load_tiles(0, 0);
    load_tiles(1, BK);

    const int NIT = CD / BK;
    for (int it = 0; it < NIT; ++it) {
        asm volatile("cp.async.wait_group 1;");
        __syncthreads();
        if (it + 2 < NIT) load_tiles((it + 2) % NSTG, (it + 2) * BK);
        else              cpasync_commit();

        int buf = it % NSTG;
        #pragma unroll
        for (int kk = 0; kk < BK; kk += 8) {
            wmma::fragment<wmma::matrix_a, 16, 16, 8, wmma::precision::tf32, wmma::row_major> af[2];
            wmma::fragment<wmma::matrix_b, 16, 16, 8, wmma::precision::tf32, wmma::row_major> bf[2];
            #pragma unroll
            for (int i = 0; i < 2; i++)
                wmma::load_matrix_sync(af[i], &sm.ab.a[buf][(wr * 32 + i * 16) * LDA + kk], LDA);
            #pragma unroll
            for (int j = 0; j < 2; j++)
                wmma::load_matrix_sync(bf[j], &sm.ab.b[buf][kk * LDB + wc * 32 + j * 16], LDB);
            #pragma unroll
            for (int i = 0; i < 2; i++)
                #pragma unroll
                for (int j = 0; j < 2; j++)
                    wmma::mma_sync(acc[i][j], af[i], bf[j], acc[i][j]);
        }
        __syncthreads();
    }

    #pragma unroll
    for (int i = 0; i < 2; i++)
        #pragma unroll
        for (int j = 0; j < 2; j++)
            wmma::store_matrix_sync(&sm.c[(wr * 32 + i * 16) * LDC + wc * 32 + j * 16],
                                    acc[i][j], LDC, wmma::mem_row_major);
    __syncthreads();

    #pragma unroll
    for (int i = 0; i < 8; i++) {
        int id = i * 256 + tid;
        int r = id >> 4, c4 = id & 15;
        float4 v = *(float4*)&sm.c[r * LDC + c4 * 4];
        int col = n0 + c4 * 4;
        v.x += bias[col]; v.y += bias[col + 1]; v.z += bias[col + 2]; v.w += bias[col + 3];
        *(float4*)&out[(size_t)(m0 + r) * CD + col] = v;
    }
}

// ---------------- launch -----------------------------------------------------
extern "C" void kernel_launch(void* const* d_in, const int* in_sizes, int n_in,
                              void* d_out, int out_size)
{
    const float* query  = (const float*)d_in[0];
    const float* memory = (const float*)d_in[1];
    const float* refp   = (const float*)d_in[2];
    const float* Wv     = (const float*)d_in[3];
    const float* bv     = (const float*)d_in[4];
    const float* Woff   = (const float*)d_in[5];
    const float* boff   = (const float*)d_in[6];
    const float* Wattn  = (const float*)d_in[7];
    const float* battn  = (const float*)d_in[8];
    const float* Wout   = (const float*)d_in[9];
    const float* bout   = (const float*)d_in[10];
    float* out = (float*)d_out;

    // 0) pre-round weights to tf32
    k_roundW<<<CD * CD / 256, 256>>>(Wv, Wout, Woff, Wattn);

    // 1a) offsets/logits GEMM (64 CTAs, single wave)
    k_offgemm<<<NQ / 128, 256>>>(query);

    // 1b) softmax + pixel coords
    k_finalize<<<NQ * 32 / 256, 256>>>(refp, boff, battn);

    // 2) dedup gather (local weight grid, one channel per thread)
    k_gather<<<NQ, 256>>>(memory, refp);

    // 3) per-head value projection (+ s*bv bias term)
    k_gemmS<<<dim3(NQ / SBM, NH), 256>>>(bv);

    // 4) output projection GEMM
    k_gemmO<<<dim3(CD / BN, NQ / BM), 256>>>(bout, out);
}